// round 8
// baseline (speedup 1.0000x reference)
#include <cuda_runtime.h>

#define THREADS 512
#define TW      120   // level-6 outputs per tile
#define NTILES  35    // ceil(4102 / 120)

// db4 reversed decomposition filters as literal immediates (FFMA-imm, rt=1)
#define RL0 ( 0.23037781330885523f)
#define RL1 ( 0.7148465705525415f)
#define RL2 ( 0.6308807679295904f)
#define RL3 (-0.02798376941698385f)
#define RL4 (-0.18703481171888114f)
#define RL5 ( 0.030841381835986965f)
#define RL6 ( 0.032883011666982945f)
#define RL7 (-0.010597401784997278f)
#define RH0 (-0.010597401784997278f)
#define RH1 (-0.032883011666982945f)
#define RH2 ( 0.030841381835986965f)
#define RH3 ( 0.18703481171888114f)
#define RH4 (-0.02798376941698385f)
#define RH5 (-0.6308807679295904f)
#define RH6 ( 0.7148465705525415f)
#define RH7 (-0.23037781330885523f)

// 8-tap A/D dot product on window starting at float2* s
#define TAPS(s, A, D) do {                                              \
    const float2 q0 = (s)[0], q1 = (s)[1], q2 = (s)[2], q3 = (s)[3];    \
    A = q0.x * RL0;            D = q0.x * RH0;                          \
    A = fmaf(q0.y, RL1, A);    D = fmaf(q0.y, RH1, D);                  \
    A = fmaf(q1.x, RL2, A);    D = fmaf(q1.x, RH2, D);                  \
    A = fmaf(q1.y, RL3, A);    D = fmaf(q1.y, RH3, D);                  \
    A = fmaf(q2.x, RL4, A);    D = fmaf(q2.x, RH4, D);                  \
    A = fmaf(q2.y, RL5, A);    D = fmaf(q2.y, RH5, D);                  \
    A = fmaf(q3.x, RL6, A);    D = fmaf(q3.x, RH6, D);                  \
    A = fmaf(q3.y, RL7, A);    D = fmaf(q3.y, RH7, D);                  \
} while (0)

__global__ __launch_bounds__(THREADS)
void dwt6_kernel(const float* __restrict__ x, float* __restrict__ out)
{
    // M[l] = length of cA_l per row (l=0 is the input)
    constexpr int M[7] = {262144, 131075, 65541, 32774, 16390, 8198, 4102};
    // Output element offsets: order cA6, cD6, cD5, cD4, cD3, cD2, cD1
    constexpr long long DOFF[7] = {0, 8390848LL, 4196224LL, 2098688LL,
                                   1049728LL, 525056LL, 262528LL};

    // Max widths for TW=120: w0<=8060 (incl align-down), w1<=4026 ; +16 margins
    __shared__ __align__(16) float buf0[8076];
    __shared__ __align__(16) float buf1[4044];

    const int tile = blockIdx.x;   // 0..34
    const int row  = blockIdx.y;   // 0..63
    const int tid  = threadIdx.x;

    int lo[7], hi[7];
    lo[6] = tile * TW;
    hi[6] = min(lo[6] + TW, M[6]);
#pragma unroll
    for (int l = 5; l >= 0; --l) {
        lo[l] = max(2 * lo[l + 1] - 6, 0);
        hi[l] = min(2 * hi[l + 1], M[l]);
    }
    lo[0] &= ~3;   // 16B-align staging base (extends left by <=2 floats)

    // Stage level-0 slice into buf0 via float4 (base 16B aligned, data at +8)
    {
        const int w0 = hi[0] - lo[0];                       // even
        const float* xr = x + (size_t)row * 262144 + lo[0];
        const float4* xr4 = reinterpret_cast<const float4*>(xr);
        float4* b4 = reinterpret_cast<float4*>(buf0 + 8);
        const int n4 = w0 >> 2;
        for (int t = tid; t < n4; t += THREADS) b4[t] = xr4[t];
        if (tid < (w0 & 3)) buf0[8 + w0 - 1 - tid] = xr[w0 - 1 - tid];  // 0 or 2 tail floats
        if (tid < 16) buf0[tid < 8 ? tid : w0 + tid] = 0.0f;            // zero margins
    }
    __syncthreads();

    float* src = buf0;
    float* dst = buf1;
#pragma unroll
    for (int l = 1; l <= 6; ++l) {
        const int llo   = lo[l], lhi = hi[l];
        const int wl    = lhi - llo;
        const int shalf = lo[l - 1] >> 1;
        const int al    = tile * (TW << (6 - l));   // owned-D start (al-llo <= 186 < THREADS)

        if (l < 6 && tid < 16) dst[tid < 8 ? tid : wl + tid] = 0.0f;

        // window for output i lives at float2 index (i + 1 - shalf)
        const float2* sp = reinterpret_cast<const float2*>(src) + (llo + tid + 1 - shalf);
        float* outD = out + DOFF[l] + (size_t)row * M[l];

        if (l < 6) {
            float* dA = dst + 8 - llo;
            for (int i0 = llo + tid; i0 < lhi; i0 += 2 * THREADS, sp += 2 * THREADS) {
                float A0, D0;
                TAPS(sp, A0, D0);
                dA[i0] = A0;
                if (i0 >= al) outD[i0] = D0;
                const int i1 = i0 + THREADS;
                if (i1 < lhi) {                 // second output: always owned
                    float A1, D1;
                    TAPS(sp + THREADS, A1, D1);
                    dA[i1] = A1;
                    outD[i1] = D1;
                }
            }
        } else {
            float* outA = out + (size_t)row * M[6];
            for (int i0 = llo + tid; i0 < lhi; i0 += THREADS, sp += THREADS) {
                float A0, D0;
                TAPS(sp, A0, D0);
                outA[i0] = A0;                  // lo[6] == al: every output owned
                outD[i0] = D0;
            }
        }
        __syncthreads();
        float* t = src; src = dst; dst = t;
    }
}

extern "C" void kernel_launch(void* const* d_in, const int* in_sizes, int n_in,
                              void* d_out, int out_size)
{
    (void)in_sizes; (void)n_in; (void)out_size;
    dim3 grid(NTILES, 64);
    dwt6_kernel<<<grid, THREADS>>>((const float*)d_in[0], (float*)d_out);
}

// round 9
// speedup vs baseline: 1.1737x; 1.1737x over previous
#include <cuda_runtime.h>

#define THREADS 512
#define TW      120   // level-6 outputs per tile
#define NTILES  35    // ceil(4102 / 120)

// db4 reversed decomposition filters as literal immediates (FFMA-imm, rt=1)
#define RL0 ( 0.23037781330885523f)
#define RL1 ( 0.7148465705525415f)
#define RL2 ( 0.6308807679295904f)
#define RL3 (-0.02798376941698385f)
#define RL4 (-0.18703481171888114f)
#define RL5 ( 0.030841381835986965f)
#define RL6 ( 0.032883011666982945f)
#define RL7 (-0.010597401784997278f)
#define RH0 (-0.010597401784997278f)
#define RH1 (-0.032883011666982945f)
#define RH2 ( 0.030841381835986965f)
#define RH3 ( 0.18703481171888114f)
#define RH4 (-0.02798376941698385f)
#define RH5 (-0.6308807679295904f)
#define RH6 ( 0.7148465705525415f)
#define RH7 (-0.23037781330885523f)

// 8-tap A/D dot product on window starting at float2* s
#define TAPS(s, A, D) do {                                              \
    const float2 q0 = (s)[0], q1 = (s)[1], q2 = (s)[2], q3 = (s)[3];    \
    A = q0.x * RL0;            D = q0.x * RH0;                          \
    A = fmaf(q0.y, RL1, A);    D = fmaf(q0.y, RH1, D);                  \
    A = fmaf(q1.x, RL2, A);    D = fmaf(q1.x, RH2, D);                  \
    A = fmaf(q1.y, RL3, A);    D = fmaf(q1.y, RH3, D);                  \
    A = fmaf(q2.x, RL4, A);    D = fmaf(q2.x, RH4, D);                  \
    A = fmaf(q2.y, RL5, A);    D = fmaf(q2.y, RH5, D);                  \
    A = fmaf(q3.x, RL6, A);    D = fmaf(q3.x, RH6, D);                  \
    A = fmaf(q3.y, RL7, A);    D = fmaf(q3.y, RH7, D);                  \
} while (0)

// 8-tap A/D dot product on scalar window w[0..7]
#define TAPSW(w, A, D) do {                                             \
    A = (w)[0] * RL0;          D = (w)[0] * RH0;                        \
    A = fmaf((w)[1], RL1, A);  D = fmaf((w)[1], RH1, D);                \
    A = fmaf((w)[2], RL2, A);  D = fmaf((w)[2], RH2, D);                \
    A = fmaf((w)[3], RL3, A);  D = fmaf((w)[3], RH3, D);                \
    A = fmaf((w)[4], RL4, A);  D = fmaf((w)[4], RH4, D);                \
    A = fmaf((w)[5], RL5, A);  D = fmaf((w)[5], RH5, D);                \
    A = fmaf((w)[6], RL6, A);  D = fmaf((w)[6], RH6, D);                \
    A = fmaf((w)[7], RL7, A);  D = fmaf((w)[7], RH7, D);                \
} while (0)

__global__ __launch_bounds__(THREADS)
void dwt6_kernel(const float* __restrict__ x, float* __restrict__ out)
{
    // M[l] = length of cA_l per row (l=0 is the input)
    constexpr int M[7] = {262144, 131075, 65541, 32774, 16390, 8198, 4102};
    // Output element offsets: order cA6, cD6, cD5, cD4, cD3, cD2, cD1
    constexpr long long DOFF[7] = {0, 8390848LL, 4196224LL, 2098688LL,
                                   1049728LL, 525056LL, 262528LL};
    constexpr int N0 = 262144;

    // bufA holds cA1: w1 <= 4029 (+16 margins). bufB holds cA2/cA4: w2 <= 2010.
    __shared__ __align__(16) float bufA[4048];
    __shared__ __align__(16) float bufB[2032];

    const int tile = blockIdx.x;   // 0..34
    const int row  = blockIdx.y;   // 0..63
    const int tid  = threadIdx.x;

    int lo[7], hi[7];
    lo[6] = tile * TW;
    hi[6] = min(lo[6] + TW, M[6]);
#pragma unroll
    for (int l = 5; l >= 1; --l) {
        lo[l] = max(2 * lo[l + 1] - 6, 0);
        hi[l] = min(2 * hi[l + 1], M[l]);
    }
    lo[1] &= ~3;   // 4-align level-1 base (16B-aligned windows + STS.128)

    const float* xr = x + (size_t)row * N0;

    // ---- Level 1: straight from gmem, 4 adjacent outputs / thread ----
    {
        const int llo = lo[1], lhi = hi[1];
        const int al  = tile * (TW << 5);
        const int bl  = min(al + (TW << 5), M[1]);
        float* dA   = bufA + 8 - llo;
        float* outD = out + DOFF[1] + (size_t)row * M[1];

        if (tid < 16) bufA[tid < 8 ? tid : (lhi - llo) + tid] = 0.0f;

        for (int i0 = llo + 4 * tid; i0 < lhi; i0 += 4 * THREADS) {
            const int g = 2 * i0 - 8;              // 16B-aligned load base
            float w[16];
            if (g >= 0 && g + 16 <= N0) {
                const float4* p = reinterpret_cast<const float4*>(xr + g);
                const float4 a = p[0], b = p[1], c = p[2], d = p[3];
                w[0]=a.x;  w[1]=a.y;  w[2]=a.z;  w[3]=a.w;
                w[4]=b.x;  w[5]=b.y;  w[6]=b.z;  w[7]=b.w;
                w[8]=c.x;  w[9]=c.y;  w[10]=c.z; w[11]=c.w;
                w[12]=d.x; w[13]=d.y; w[14]=d.z; w[15]=d.w;
            } else {
#pragma unroll
                for (int k = 0; k < 16; ++k) {
                    const int idx = g + k;
                    w[k] = (idx >= 0 && idx < N0) ? xr[idx] : 0.0f;
                }
            }
            float A0, A1, A2, A3, D0, D1, D2, D3;
            TAPSW(w + 2, A0, D0);   // output i0   : x[2i0-6 .. 2i0+1]
            TAPSW(w + 4, A1, D1);
            TAPSW(w + 6, A2, D2);
            TAPSW(w + 8, A3, D3);

            if (i0 + 4 <= lhi) {
                *reinterpret_cast<float4*>(dA + i0) = make_float4(A0, A1, A2, A3);
            } else {
                dA[i0] = A0;
                if (i0 + 1 < lhi) dA[i0 + 1] = A1;
                if (i0 + 2 < lhi) dA[i0 + 2] = A2;
                if (i0 + 3 < lhi) dA[i0 + 3] = A3;
            }
            if (i0     >= al && i0     < bl) outD[i0]     = D0;
            if (i0 + 1 >= al && i0 + 1 < bl) outD[i0 + 1] = D1;
            if (i0 + 2 >= al && i0 + 2 < bl) outD[i0 + 2] = D2;
            if (i0 + 3 >= al && i0 + 3 < bl) outD[i0 + 3] = D3;
        }
        __syncthreads();
    }

    // ---- Levels 2..6: smem ping-pong, 2 strided outputs / thread ----
    float* src = bufA;
    float* dst = bufB;
#pragma unroll
    for (int l = 2; l <= 6; ++l) {
        const int llo   = lo[l], lhi = hi[l];
        const int wl    = lhi - llo;
        const int shalf = lo[l - 1] >> 1;
        const int al    = tile * (TW << (6 - l));   // al - llo <= 90 < THREADS

        if (l < 6 && tid < 16) dst[tid < 8 ? tid : wl + tid] = 0.0f;

        // window for output i lives at float2 index (i + 1 - shalf)
        const float2* sp = reinterpret_cast<const float2*>(src) + (llo + tid + 1 - shalf);
        float* outD = out + DOFF[l] + (size_t)row * M[l];

        if (l < 6) {
            float* dA = dst + 8 - llo;
            for (int i0 = llo + tid; i0 < lhi; i0 += 2 * THREADS, sp += 2 * THREADS) {
                float A0, D0;
                TAPS(sp, A0, D0);
                dA[i0] = A0;
                if (i0 >= al) outD[i0] = D0;
                const int i1 = i0 + THREADS;
                if (i1 < lhi) {                 // second output: always owned
                    float A1, D1;
                    TAPS(sp + THREADS, A1, D1);
                    dA[i1] = A1;
                    outD[i1] = D1;
                }
            }
        } else {
            float* outA = out + (size_t)row * M[6];
            for (int i0 = llo + tid; i0 < lhi; i0 += THREADS, sp += THREADS) {
                float A0, D0;
                TAPS(sp, A0, D0);
                outA[i0] = A0;                  // lo[6] == al: every output owned
                outD[i0] = D0;
            }
        }
        __syncthreads();
        float* t = src; src = dst; dst = t;
    }
}

extern "C" void kernel_launch(void* const* d_in, const int* in_sizes, int n_in,
                              void* d_out, int out_size)
{
    (void)in_sizes; (void)n_in; (void)out_size;
    dim3 grid(NTILES, 64);
    dwt6_kernel<<<grid, THREADS>>>((const float*)d_in[0], (float*)d_out);
}